// round 1
// baseline (speedup 1.0000x reference)
#include <cuda_runtime.h>
#include <cstdint>

#define NFEAT 256
#define NHID  128
#define MAX_NODES 50000

// Scratch for support = x @ W  (25.6 MB, static device global per allocation rules)
__device__ float g_support[(size_t)MAX_NODES * NHID];

// ---------------------------------------------------------------------------
// SGEMM: out[M,128] = x[M,256] @ w[256,128]
// BM=64, BN=128 (full N), BK=16, 256 threads, 8x4 register tile per thread.
// ---------------------------------------------------------------------------
__global__ __launch_bounds__(256) void gemm_kernel(
    const float* __restrict__ x, const float* __restrict__ w,
    float* __restrict__ out, int M)
{
    __shared__ float As[16][64];    // [k][row] (transposed so compute loads are vectorizable)
    __shared__ float Bs[16][128];   // [k][col]

    const int tid = threadIdx.x;
    const int block_row = blockIdx.x * 64;
    const int tx = tid & 31;   // col group: cols tx*4 .. tx*4+3
    const int ty = tid >> 5;   // row group: rows ty*8 .. ty*8+7

    float acc[8][4];
#pragma unroll
    for (int i = 0; i < 8; i++)
#pragma unroll
        for (int j = 0; j < 4; j++) acc[i][j] = 0.f;

    for (int k0 = 0; k0 < NFEAT; k0 += 16) {
        // Load A tile: 64 rows x 16 k. Thread t loads float4 at (row=t/4, k=(t%4)*4).
        {
            int r  = tid >> 2;
            int kk = (tid & 3) * 4;
            int grow = block_row + r;
            float4 v = make_float4(0.f, 0.f, 0.f, 0.f);
            if (grow < M)
                v = *(const float4*)(x + (size_t)grow * NFEAT + k0 + kk);
            As[kk + 0][r] = v.x;
            As[kk + 1][r] = v.y;
            As[kk + 2][r] = v.z;
            As[kk + 3][r] = v.w;
        }
        // Load B tile: 16 x 128 floats = 512 float4; 2 per thread.
        {
#pragma unroll
            for (int l = 0; l < 2; l++) {
                int idx = tid + l * 256;        // 0..511
                int kk  = idx >> 5;             // 32 float4 per 128-wide row
                int c4  = (idx & 31) * 4;
                float4 v = *(const float4*)(w + (size_t)(k0 + kk) * NHID + c4);
                *(float4*)&Bs[kk][c4] = v;
            }
        }
        __syncthreads();

#pragma unroll
        for (int kk = 0; kk < 16; kk++) {
            float a[8];
            float4 a0 = *(const float4*)&As[kk][ty * 8];
            float4 a1 = *(const float4*)&As[kk][ty * 8 + 4];
            a[0] = a0.x; a[1] = a0.y; a[2] = a0.z; a[3] = a0.w;
            a[4] = a1.x; a[5] = a1.y; a[6] = a1.z; a[7] = a1.w;
            float4 b = *(const float4*)&Bs[kk][tx * 4];
#pragma unroll
            for (int i = 0; i < 8; i++) {
                acc[i][0] += a[i] * b.x;
                acc[i][1] += a[i] * b.y;
                acc[i][2] += a[i] * b.z;
                acc[i][3] += a[i] * b.w;
            }
        }
        __syncthreads();
    }

#pragma unroll
    for (int i = 0; i < 8; i++) {
        int grow = block_row + ty * 8 + i;
        if (grow < M) {
            float4 v = make_float4(acc[i][0], acc[i][1], acc[i][2], acc[i][3]);
            *(float4*)(out + (size_t)grow * NHID + tx * 4) = v;
        }
    }
}

// ---------------------------------------------------------------------------
// Zero d_out (it is poisoned to 0xAA; we atomically accumulate into it).
// ---------------------------------------------------------------------------
__global__ void zero_kernel(float4* __restrict__ p, int n4)
{
    int i = blockIdx.x * blockDim.x + threadIdx.x;
    if (i < n4) p[i] = make_float4(0.f, 0.f, 0.f, 0.f);
}

// ---------------------------------------------------------------------------
// Edge scatter: agg[dst] += support[src] * ew.
// Warp handles 32 edges: coalesced index loads, shfl-broadcast per edge,
// 32 lanes x float4 covers one 128-float row; vectorized red.global.add.
// ---------------------------------------------------------------------------
__global__ __launch_bounds__(256) void scatter_kernel(
    const float* __restrict__ support,
    const int*   __restrict__ src,
    const int*   __restrict__ dst,
    const float* __restrict__ ew,
    float*       __restrict__ agg,
    int E)
{
    int warp = (blockIdx.x * blockDim.x + threadIdx.x) >> 5;
    int lane = threadIdx.x & 31;
    int e0 = warp * 32;
    if (e0 >= E) return;
    int n = E - e0; if (n > 32) n = 32;

    int s_l = 0, d_l = 0; float w_l = 0.f;
    if (lane < n) {
        s_l = src[e0 + lane];
        d_l = dst[e0 + lane];
        w_l = ew[e0 + lane];
    }

    for (int i = 0; i < n; i++) {
        int   s = __shfl_sync(0xffffffffu, s_l, i);
        int   d = __shfl_sync(0xffffffffu, d_l, i);
        float w = __shfl_sync(0xffffffffu, w_l, i);

        float4 v = *(const float4*)(support + (size_t)s * NHID + lane * 4);
        v.x *= w; v.y *= w; v.z *= w; v.w *= w;

        float* p = agg + (size_t)d * NHID + lane * 4;
        asm volatile("red.global.add.v4.f32 [%0], {%1, %2, %3, %4};"
                     :: "l"(p), "f"(v.x), "f"(v.y), "f"(v.z), "f"(v.w)
                     : "memory");
    }
}

// ---------------------------------------------------------------------------
// Finalize: h = relu(agg + bias); out = h - max(h) - log(sum(exp(h - max)))
// One warp per row; lane owns 4 contiguous floats (float4).
// ---------------------------------------------------------------------------
__global__ __launch_bounds__(256) void finalize_kernel(
    float* __restrict__ out, const float* __restrict__ bias, int M)
{
    int warp = (blockIdx.x * blockDim.x + threadIdx.x) >> 5;
    int lane = threadIdx.x & 31;
    if (warp >= M) return;

    float* row = out + (size_t)warp * NHID;
    float4 b = *(const float4*)(bias + lane * 4);
    float4 h = *(const float4*)(row + lane * 4);

    h.x = fmaxf(h.x + b.x, 0.f);
    h.y = fmaxf(h.y + b.y, 0.f);
    h.z = fmaxf(h.z + b.z, 0.f);
    h.w = fmaxf(h.w + b.w, 0.f);

    float m = fmaxf(fmaxf(h.x, h.y), fmaxf(h.z, h.w));
#pragma unroll
    for (int o = 16; o > 0; o >>= 1)
        m = fmaxf(m, __shfl_xor_sync(0xffffffffu, m, o));

    float s = expf(h.x - m) + expf(h.y - m) + expf(h.z - m) + expf(h.w - m);
#pragma unroll
    for (int o = 16; o > 0; o >>= 1)
        s += __shfl_xor_sync(0xffffffffu, s, o);

    float lse = m + logf(s);
    h.x -= lse; h.y -= lse; h.z -= lse; h.w -= lse;
    *(float4*)(row + lane * 4) = h;
}

// ---------------------------------------------------------------------------
// Launch. Inputs (metadata order): x[f32 M*256], weight[f32 256*128],
// bias[f32 128], edge_index[i32 2*E], edge_weight[f32 E]. Output f32 M*128.
// ---------------------------------------------------------------------------
extern "C" void kernel_launch(void* const* d_in, const int* in_sizes, int n_in,
                              void* d_out, int out_size)
{
    const float* x    = (const float*)d_in[0];
    const float* w    = (const float*)d_in[1];
    const float* bias = (const float*)d_in[2];
    const int*   ei   = (const int*)d_in[3];
    const float* ew   = (const float*)d_in[4];
    float* out = (float*)d_out;

    const int M = in_sizes[0] / NFEAT;      // 50000
    const int E = in_sizes[4];              // 1,600,000
    const int* src = ei;                    // edge_index[0]
    const int* dst = ei + E;                // edge_index[1]

    float* support;
    cudaGetSymbolAddress((void**)&support, g_support);

    // 1) support = x @ W
    gemm_kernel<<<(M + 63) / 64, 256>>>(x, w, support, M);

    // 2) zero the accumulator (d_out)
    int n4 = M * (NHID / 4);
    zero_kernel<<<(n4 + 255) / 256, 256>>>((float4*)out, n4);

    // 3) scatter-add messages
    int warps = (E + 31) / 32;
    int blocks = (warps + 7) / 8;           // 8 warps / 256-thread block
    scatter_kernel<<<blocks, 256>>>(support, src, dst, ew, out, E);

    // 4) bias + relu + log_softmax (in place on d_out)
    finalize_kernel<<<(M + 7) / 8, 256>>>(out, bias, M);
}